// round 15
// baseline (speedup 1.0000x reference)
#include <cuda_runtime.h>
#include <cuda_fp16.h>
#include <math.h>
#include <stdint.h>

// ---------------- problem constants ----------------
#define BB    512
#define TT    96
#define DIN   64
#define HH    256
#define LL    4
#define EE    768
#define NCC   100
#define TP    48
#define FF    25
#define NF2   13
#define DHH   96
#define NHEADS 8

#define N_BT  ((size_t)BB * TT)   // 49152
#define N_BF  ((size_t)BB * FF)   // 12800

#define SPLIT_C63_64  0.984375f
#define FINAL_SCALE   0.9846153846153846f

// ---------------- scratch buffers ----------------
__device__ __align__(16) float g_h1 [N_BT * HH];
__device__ __align__(16) float g_hpe[N_BT * HH];
__device__ __align__(16) float g_hp [(size_t)BB * TP * HH];
__device__ __align__(16) float g_fr [N_BF * HH];
__device__ __align__(16) float g_C48[FF * TP];
__device__ __align__(16) float g_cb [EE];
__device__ __align__(16) float g_h  [N_BF * EE];
__device__ __align__(16) float g_qkv[N_BF * 3 * EE];
__device__ __align__(16) float g_s  [N_BF * EE];
__device__ __align__(16) float g_hm [(size_t)BB * EE];

// split-fp16 GEMM-A buffers
__device__ __align__(16) __half g_xs1 [N_BT * DIN],      g_xs2 [N_BT * DIN];
__device__ __align__(16) __half g_sf1 [N_BT * HH],       g_sf2 [N_BT * HH];
__device__ __align__(16) __half g_h21 [N_BT * HH],       g_h22 [N_BT * HH];
__device__ __align__(16) __half g_col1[N_BF * 2304],     g_col2[N_BF * 2304];
__device__ __align__(16) __half g_y1  [N_BF * EE],       g_y2  [N_BF * EE];
__device__ __align__(16) __half g_att1[N_BF * EE],       g_att2[N_BF * EE];
__device__ __align__(16) __half g_mid1[N_BF * 4 * EE],   g_mid2[N_BF * 4 * EE];

// transposed fp16 weights [N][K]
__device__ __align__(16) __half g_tWin_h [256 * 64],       g_tWin_2 [256 * 64];
__device__ __align__(16) __half g_tWsh_h [256 * 256],      g_tWsh_2 [256 * 256];
__device__ __align__(16) __half g_tWpa_h [256 * 512],      g_tWpa_2 [256 * 512];
__device__ __align__(16) __half g_tWc_h  [768 * 1024],     g_tWc_2  [768 * 1024];
__device__ __align__(16) __half g_tWqkv_h[LL * 2304 * 768],g_tWqkv_2[LL * 2304 * 768];
__device__ __align__(16) __half g_tWo_h  [LL * 768 * 768], g_tWo_2  [LL * 768 * 768];
__device__ __align__(16) __half g_tWf1_h [LL * 3072 * 768],g_tWf1_2 [LL * 3072 * 768];
__device__ __align__(16) __half g_tWf2_h [LL * 768 * 3072],g_tWf2_2 [LL * 768 * 3072];
__device__ __align__(16) __half g_tWc2_h [768 * 2304],     g_tWc2_2 [768 * 2304];

// ---------------- helpers ----------------
__device__ __forceinline__ uint32_t smem_u32(const void* p) {
    uint32_t a;
    asm("{ .reg .u64 t; cvta.to.shared.u64 t, %1; cvt.u32.u64 %0, t; }" : "=r"(a) : "l"(p));
    return a;
}
__device__ __forceinline__ uint32_t hpack(__half a, __half b) {
    __half2 t; t.x = a; t.y = b;
    return *reinterpret_cast<uint32_t*>(&t);
}

__device__ __forceinline__ void splitS(float a, __half& x1, __half& x2) {
    x1 = __float2half_rn(a);
    x2 = __float2half_rn(fmaf(-SPLIT_C63_64, __half2float(x1), a));
}
__device__ __forceinline__ void splitB(float w, __half& b1, __half& b2) {
    b1 = __float2half_rn(w);
    float b1f = __half2float(b1);
    b2 = __float2half_rn(fmaf(64.f, w - b1f, b1f));
}
__device__ __forceinline__ void splitS4(float4 v, uint2& o1, uint2& o2) {
    __half a0, b0, a1, b1, a2, b2, a3, b3;
    splitS(v.x, a0, b0); splitS(v.y, a1, b1);
    splitS(v.z, a2, b2); splitS(v.w, a3, b3);
    o1 = make_uint2(hpack(a0, a1), hpack(a2, a3));
    o2 = make_uint2(hpack(b0, b1), hpack(b2, b3));
}

#define SWZ128(x) ((x) ^ (((x) >> 3) & 0x70))

#define LDMX4(r, a) \
    asm volatile("ldmatrix.sync.aligned.m8n8.x4.shared.b16 {%0,%1,%2,%3}, [%4];" \
        : "=r"((r)[0]), "=r"((r)[1]), "=r"((r)[2]), "=r"((r)[3]) : "r"(a))
#define MMA16816(d, A, Bf) \
    asm volatile("mma.sync.aligned.m16n8k16.row.col.f32.f16.f16.f32 " \
        "{%0,%1,%2,%3}, {%4,%5,%6,%7}, {%8,%9}, {%0,%1,%2,%3};" \
        : "+f"((d)[0]), "+f"((d)[1]), "+f"((d)[2]), "+f"((d)[3]) \
        : "r"((A)[0]), "r"((A)[1]), "r"((A)[2]), "r"((A)[3]), "r"((Bf)[0]), "r"((Bf)[1]))

#define CP_ASYNC16(dst, src) \
    asm volatile("cp.async.cg.shared.global [%0], [%1], 16;" :: "r"(dst), "l"(src))
#define CP_COMMIT()  asm volatile("cp.async.commit_group;" ::: "memory")
#define CP_WAIT1()   asm volatile("cp.async.wait_group 1;" ::: "memory")

// ---------------- HMMA GEMM (R12 mainloop; single-pass epilogue) ----------------
#define G6_A      0
#define G6_B      16384
#define G6_STAGE  32768
#define G6_TOTAL  98304

__global__ void __launch_bounds__(256, 2)
gemm_mma_kernel(const __half* __restrict__ A1, const __half* __restrict__ A2,
                const __half* __restrict__ B1g, const __half* __restrict__ B2g,
                float* __restrict__ Cf, __half* __restrict__ C1, __half* __restrict__ C2,
                int M, int N, int K,
                const float* __restrict__ bias, const float* __restrict__ res, int act)
{
    extern __shared__ char smem[];
    const uint32_t sb = smem_u32(smem);
    const int tid  = threadIdx.x;
    const int lane = tid & 31;
    const int wid  = tid >> 5;
    const int wm   = wid & 1;
    const int wn   = wid >> 1;
    const int m0 = blockIdx.y * 128;
    const int n0 = blockIdx.x * 128;

    const int ldRow  = tid >> 1;
    const int ldHalf = tid & 1;

    float acc[4][4][4];
#pragma unroll
    for (int i = 0; i < 4; i++)
#pragma unroll
        for (int j = 0; j < 4; j++)
#pragma unroll
            for (int e = 0; e < 4; e++) acc[i][j][e] = 0.f;

    const int nk = K >> 5;

    const uint32_t aBase = (uint32_t)(wm * 64 + (lane & 15)) * 128u + (uint32_t)(lane >> 4) * 16u;
    const uint32_t bBase = (uint32_t)(wn * 32 + (lane >> 4) * 8 + (lane & 7)) * 128u
                         + (uint32_t)((lane >> 3) & 1) * 16u;

    auto issueStage = [&](int kc, uint32_t bufb) {
        const __half* A1p = A1 + (size_t)(m0 + ldRow) * K + kc * 32;
        const __half* A2p = A2 + (size_t)(m0 + ldRow) * K + kc * 32;
        const __half* B1p = B1g + (size_t)(n0 + ldRow) * K + kc * 32;
        const __half* B2p = B2g + (size_t)(n0 + ldRow) * K + kc * 32;
#pragma unroll
        for (int j = 0; j < 2; j++) {
            int c = ldHalf * 2 + j;
            uint32_t r1 = (uint32_t)ldRow * 128u + (uint32_t)c * 16u;
            CP_ASYNC16(sb + bufb + G6_A + SWZ128(r1),       A1p + c * 8);
            CP_ASYNC16(sb + bufb + G6_A + SWZ128(r1 + 64u), A2p + c * 8);
            CP_ASYNC16(sb + bufb + G6_B + SWZ128(r1),       B1p + c * 8);
            CP_ASYNC16(sb + bufb + G6_B + SWZ128(r1 + 64u), B2p + c * 8);
        }
    };

    issueStage(0, 0);
    CP_COMMIT();
    if (1 < nk) issueStage(1, G6_STAGE);
    CP_COMMIT();

    int stage = 0;
    for (int kc = 0; kc < nk; kc++) {
        CP_WAIT1();
        __syncthreads();
        if (kc + 2 < nk) {
            int ns = stage + 2; if (ns >= 3) ns -= 3;
            issueStage(kc + 2, (uint32_t)ns * G6_STAGE);
        }
        CP_COMMIT();
        const uint32_t bufo = (uint32_t)stage * G6_STAGE;
#pragma unroll
        for (int kk = 0; kk < 2; kk++) {
            const uint32_t kb = (uint32_t)kk * 32u;
            const uint32_t a1Sw = SWZ128(aBase + kb);
            const uint32_t a2Sw = SWZ128(aBase + kb + 64u);
            const uint32_t b1Sw = SWZ128(bBase + kb);
            const uint32_t b2Sw = SWZ128(bBase + kb + 64u);
            uint32_t b1f[2][4], b2f[2][4];
#pragma unroll
            for (int ni2 = 0; ni2 < 2; ni2++) {
                uint32_t b_addr = sb + bufo + G6_B + (uint32_t)(ni2 * 2048);
                LDMX4(b1f[ni2], b_addr + b1Sw);
                LDMX4(b2f[ni2], b_addr + b2Sw);
            }
#pragma unroll
            for (int mi = 0; mi < 4; mi++) {
                uint32_t x1f[4], x2f[4];
                uint32_t a_addr = sb + bufo + G6_A + (uint32_t)(mi * 2048);
                LDMX4(x1f, a_addr + a1Sw);
                LDMX4(x2f, a_addr + a2Sw);
#pragma unroll
                for (int ni = 0; ni < 4; ni++) {
                    MMA16816(acc[mi][ni], x1f, &b1f[ni >> 1][(ni & 1) * 2]);
                    MMA16816(acc[mi][ni], x2f, &b2f[ni >> 1][(ni & 1) * 2]);
                }
            }
        }
        if (++stage == 3) stage = 0;
    }
    __syncthreads();

    // single-pass epilogue: full 128x132 f32 staging (67.6KB < 96KB smem)
    float* stg = reinterpret_cast<float*>(smem);
#pragma unroll
    for (int mi = 0; mi < 4; mi++) {
#pragma unroll
        for (int ni = 0; ni < 4; ni++) {
            int r = wm * 64 + mi * 16 + (lane >> 2);
            int c = wn * 32 + ni * 8 + (lane & 3) * 2;
            stg[r * 132 + c]           = acc[mi][ni][0];
            stg[r * 132 + c + 1]       = acc[mi][ni][1];
            stg[(r + 8) * 132 + c]     = acc[mi][ni][2];
            stg[(r + 8) * 132 + c + 1] = acc[mi][ni][3];
        }
    }
    __syncthreads();
#pragma unroll 4
    for (int it = 0; it < 64; it++) {
        int idx = it * 256 + tid;
        int r = idx >> 7, c = idx & 127;
        float v = stg[r * 132 + c] * FINAL_SCALE;
        int gn = n0 + c;
        size_t gr = (size_t)(m0 + r);
        if (bias) v += bias[gn];
        if (res)  v += res[gr * N + gn];
        if (act)  v = 0.5f * v * (1.0f + erff(v * 0.70710678118654752f));
        if (C1) {
            __half o1, o2;
            splitS(v, o1, o2);
            C1[gr * N + gn] = o1;
            C2[gr * N + gn] = o2;
        } else {
            Cf[gr * N + gn] = v;
        }
    }
}

// ---------------- fallback f32 SGEMM (classifier only) ----------------
__global__ void __launch_bounds__(256, 2)
sgemm_kernel(const float* __restrict__ A, const float* __restrict__ B,
             float* __restrict__ C, int M, int N, int K,
             const float* __restrict__ bias)
{
    __shared__ float As[8][128];
    __shared__ float Bs[8][128];
    const int tid = threadIdx.x;
    const int row0 = blockIdx.y * 128, col0 = blockIdx.x * 128;
    const int tx = tid & 15, ty = tid >> 4;
    const int arow = tid >> 1, acol = (tid & 1) * 4;
    const int brow = tid >> 5, bcol = (tid & 31) * 4;
    float acc[8][8];
#pragma unroll
    for (int i = 0; i < 8; i++)
#pragma unroll
        for (int j = 0; j < 8; j++) acc[i][j] = 0.f;
    const int gar = row0 + arow, gbc = col0 + bcol;
    const bool aok = (gar < M), bok = (gbc < N);
    for (int k0 = 0; k0 < K; k0 += 8) {
        float4 avv = make_float4(0, 0, 0, 0);
        if (aok) avv = *reinterpret_cast<const float4*>(&A[(size_t)gar * K + k0 + acol]);
        As[acol + 0][arow] = avv.x; As[acol + 1][arow] = avv.y;
        As[acol + 2][arow] = avv.z; As[acol + 3][arow] = avv.w;
        float4 bv = make_float4(0, 0, 0, 0);
        if (bok) bv = *reinterpret_cast<const float4*>(&B[(size_t)(k0 + brow) * N + gbc]);
        *reinterpret_cast<float4*>(&Bs[brow][bcol]) = bv;
        __syncthreads();
#pragma unroll
        for (int kk = 0; kk < 8; kk++) {
            float4 ra0 = *reinterpret_cast<const float4*>(&As[kk][ty * 8 + 0]);
            float4 ra1 = *reinterpret_cast<const float4*>(&As[kk][ty * 8 + 4]);
            float4 rb0 = *reinterpret_cast<const float4*>(&Bs[kk][tx * 8 + 0]);
            float4 rb1 = *reinterpret_cast<const float4*>(&Bs[kk][tx * 8 + 4]);
            float ra[8] = {ra0.x, ra0.y, ra0.z, ra0.w, ra1.x, ra1.y, ra1.z, ra1.w};
            float rb[8] = {rb0.x, rb0.y, rb0.z, rb0.w, rb1.x, rb1.y, rb1.z, rb1.w};
#pragma unroll
            for (int i = 0; i < 8; i++)
#pragma unroll
                for (int j = 0; j < 8; j++) acc[i][j] = fmaf(ra[i], rb[j], acc[i][j]);
        }
        __syncthreads();
    }
#pragma unroll
    for (int i = 0; i < 8; i++) {
        const int r = row0 + ty * 8 + i;
        if (r >= M) continue;
#pragma unroll
        for (int j = 0; j < 8; j++) {
            const int c = col0 + tx * 8 + j;
            if (c >= N) continue;
            float v = acc[i][j];
            if (bias) v += bias[c];
            C[(size_t)r * N + c] = v;
        }
    }
}

// ---------------- weight transpose + split: 64x64 tiles, vectorized ----------------
__global__ void __launch_bounds__(256) tsplit_kernel(const float* __restrict__ W,
                                                     __half* __restrict__ b1,
                                                     __half* __restrict__ b2, int K, int N)
{
    __shared__ float t[64][65];
    const int k0 = blockIdx.y * 64, n0 = blockIdx.x * 64;
    const int tid = threadIdx.x;
    const int tx = tid & 15, ty = tid >> 4;
#pragma unroll
    for (int r = 0; r < 4; r++) {
        int kl = ty + r * 16;
        float4 v = *reinterpret_cast<const float4*>(&W[(size_t)(k0 + kl) * N + n0 + tx * 4]);
        t[kl][tx * 4 + 0] = v.x;
        t[kl][tx * 4 + 1] = v.y;
        t[kl][tx * 4 + 2] = v.z;
        t[kl][tx * 4 + 3] = v.w;
    }
    __syncthreads();
    const int kq = tid & 15, nr = tid >> 4;
#pragma unroll
    for (int r = 0; r < 4; r++) {
        int nl = nr + r * 16;
        __half h1[4], h2[4];
#pragma unroll
        for (int j = 0; j < 4; j++)
            splitB(t[kq * 4 + j][nl], h1[j], h2[j]);
        size_t off = (size_t)(n0 + nl) * K + k0 + kq * 4;
        *reinterpret_cast<uint2*>(&b1[off]) = make_uint2(hpack(h1[0], h1[1]), hpack(h1[2], h1[3]));
        *reinterpret_cast<uint2*>(&b2[off]) = make_uint2(hpack(h2[0], h2[1]), hpack(h2[2], h2[3]));
    }
}

__global__ void assemble_conv_wT(const float* __restrict__ w1, const float* __restrict__ w2,
                                 const float* __restrict__ w4, const float* __restrict__ b1c,
                                 const float* __restrict__ b2c, const float* __restrict__ b4c,
                                 __half* __restrict__ o1, __half* __restrict__ o2,
                                 float* __restrict__ cb)
{
    int q = blockIdx.x * blockDim.x + threadIdx.x;
    if (q < EE) cb[q] = (q < 256) ? b1c[q] : (q < 512 ? b2c[q - 256] : b4c[q - 512]);
    if (q >= 768 * 256) return;
    int n = q >> 8, kq = q & 255;
    int d = kq >> 6;
    int i = (kq & 63) * 4;
    float v[4] = {0.f, 0.f, 0.f, 0.f};
    if (n < 256) {
        if (d == 1) {
            float4 t = *reinterpret_cast<const float4*>(&w1[n * 256 + i]);
            v[0] = t.x; v[1] = t.y; v[2] = t.z; v[3] = t.w;
        }
    } else if (n < 512) {
        int oo = n - 256, j = d - 1;
        if (j == 0 || j == 1)
#pragma unroll
            for (int e = 0; e < 4; e++) v[e] = w2[oo * 512 + (i + e) * 2 + j];
    } else {
        int oo = n - 512;
#pragma unroll
        for (int e = 0; e < 4; e++) v[e] = w4[oo * 1024 + (i + e) * 4 + d];
    }
    __half h1[4], h2[4];
#pragma unroll
    for (int e = 0; e < 4; e++) splitB(v[e], h1[e], h2[e]);
    size_t off = (size_t)q * 4;
    *reinterpret_cast<uint2*>(&o1[off]) = make_uint2(hpack(h1[0], h1[1]), hpack(h1[2], h1[3]));
    *reinterpret_cast<uint2*>(&o2[off]) = make_uint2(hpack(h2[0], h2[1]), hpack(h2[2], h2[3]));
}

__global__ void assemble_ssm_wT(const float* __restrict__ w, __half* __restrict__ o1,
                                __half* __restrict__ o2)
{
    int q = blockIdx.x * blockDim.x + threadIdx.x;
    if (q >= 768 * 576) return;
    int n = q / 576, kq = q % 576;
    int j = kq / 192;
    int i = (kq % 192) * 4;
    __half h1[4], h2[4];
#pragma unroll
    for (int e = 0; e < 4; e++)
        splitB(w[(size_t)n * 2304 + (i + e) * 3 + j], h1[e], h2[e]);
    size_t off = (size_t)q * 4;
    *reinterpret_cast<uint2*>(&o1[off]) = make_uint2(hpack(h1[0], h1[1]), hpack(h1[2], h1[3]));
    *reinterpret_cast<uint2*>(&o2[off]) = make_uint2(hpack(h2[0], h2[1]), hpack(h2[2], h2[3]));
}

// ---------------- small kernels ----------------
__global__ void init_c48_kernel(float* __restrict__ C48) {
    for (int i = threadIdx.x; i < FF * TP; i += blockDim.x) {
        int k = i / TP, t = i % TP;
        int m = (k * t) % TP;
        C48[i] = cospif(2.0f * (float)m / (float)TP);
    }
}

__global__ void split_x_kernel(const float* __restrict__ x, __half* __restrict__ x1,
                               __half* __restrict__ x2, size_t nquads)
{
    size_t q = (size_t)blockIdx.x * blockDim.x + threadIdx.x;
    if (q >= nquads) return;
    float4 v = reinterpret_cast<const float4*>(x)[q];
    uint2 o1, o2;
    splitS4(v, o1, o2);
    reinterpret_cast<uint2*>(x1)[q] = o1;
    reinterpret_cast<uint2*>(x2)[q] = o2;
}

__global__ void pe_diff_kernel(const float* __restrict__ h1, const float* __restrict__ pe,
                               float* __restrict__ hpe, __half* __restrict__ sf1,
                               __half* __restrict__ sf2)
{
    size_t q = (size_t)blockIdx.x * blockDim.x + threadIdx.x;
    const size_t nquads = N_BT * HH / 4;
    if (q >= nquads) return;
    int cq = (int)(q % (HH / 4));
    size_t r = q / (HH / 4);
    int t = (int)(r % TT);
    float4 hv = reinterpret_cast<const float4*>(h1)[q];
    float4 pv = reinterpret_cast<const float4*>(pe)[(size_t)t * (HH / 4) + cq];
    float4 cur = make_float4(hv.x + pv.x, hv.y + pv.y, hv.z + pv.z, hv.w + pv.w);
    reinterpret_cast<float4*>(hpe)[q] = cur;
    float4 prev;
    if (t == 0) {
        prev = cur;
    } else {
        float4 hv0 = reinterpret_cast<const float4*>(h1)[q - HH / 4];
        float4 pv0 = reinterpret_cast<const float4*>(pe)[(size_t)(t - 1) * (HH / 4) + cq];
        prev = make_float4(hv0.x + pv0.x, hv0.y + pv0.y, hv0.z + pv0.z, hv0.w + pv0.w);
    }
    float4 d = make_float4(cur.x - prev.x, cur.y - prev.y, cur.z - prev.z, cur.w - prev.w);
    uint2 o1, o2;
    splitS4(d, o1, o2);
    reinterpret_cast<uint2*>(sf1)[q] = o1;
    reinterpret_cast<uint2*>(sf2)[q] = o2;
}

__global__ void __launch_bounds__(256) dft48_kernel(const float* __restrict__ hp,
                                                    float* __restrict__ out,
                                                    const float* __restrict__ C48)
{
    __shared__ float sC[FF * TP];
    int b = blockIdx.x;
    for (int i = threadIdx.x; i < FF * TP; i += 256) sC[i] = C48[i];
    float r[TP];
    const float* base = hp + (size_t)b * TP * HH + threadIdx.x;
#pragma unroll
    for (int t = 0; t < TP; t++) r[t] = base[(size_t)t * HH];
    __syncthreads();
    float* ob = out + (size_t)b * FF * HH + threadIdx.x;
    for (int k = 0; k < FF; k++) {
        float acc = 0.f;
#pragma unroll
        for (int t = 0; t < TP; t++) acc = fmaf(r[t], sC[k * TP + t], acc);
        ob[(size_t)k * HH] = acc;
    }
}

__global__ void im2col_conv(const float* __restrict__ f, __half* __restrict__ c1,
                            __half* __restrict__ c2)
{
    size_t q = (size_t)blockIdx.x * blockDim.x + threadIdx.x;
    const size_t nquads = N_BF * 256;
    if (q >= nquads) return;
    int kq = (int)(q % 256);
    size_t row = q / 256;
    int d = kq / 64;
    int i = (kq % 64) * 4;
    int fq = (int)(row % FF);
    size_t b = row / FF;
    int src = fq + d - 1;
    float4 v = make_float4(0.f, 0.f, 0.f, 0.f);
    if (src >= 0 && src < FF)
        v = *reinterpret_cast<const float4*>(&f[((size_t)b * FF + src) * HH + i]);
    uint2 o1, o2;
    splitS4(v, o1, o2);
    reinterpret_cast<uint2*>(c1)[q] = o1;
    reinterpret_cast<uint2*>(c2)[q] = o2;
}

__global__ void im2col_ssm(const float* __restrict__ h, __half* __restrict__ c1,
                           __half* __restrict__ c2)
{
    size_t q = (size_t)blockIdx.x * blockDim.x + threadIdx.x;
    const size_t nquads = N_BF * 576;
    if (q >= nquads) return;
    int kq = (int)(q % 576);
    size_t row = q / 576;
    int j = kq / 192;
    int i = (kq % 192) * 4;
    int fq = (int)(row % FF);
    size_t b = row / FF;
    int src = fq + j - 1;
    float4 v = make_float4(0.f, 0.f, 0.f, 0.f);
    if (src >= 0 && src < FF)
        v = *reinterpret_cast<const float4*>(&h[((size_t)b * FF + src) * EE + i]);
    uint2 o1, o2;
    splitS4(v, o1, o2);
    reinterpret_cast<uint2*>(c1)[q] = o1;
    reinterpret_cast<uint2*>(c2)[q] = o2;
}

__global__ void __launch_bounds__(256) ln_kernel(const float* __restrict__ x,
                                                 const float* __restrict__ g,
                                                 const float* __restrict__ bta,
                                                 __half* __restrict__ y1,
                                                 __half* __restrict__ y2, int C)
{
    int row = blockIdx.x;
    const float* xr = x + (size_t)row * C;
    float vals[3];
    float s = 0.f, q = 0.f;
#pragma unroll
    for (int r = 0; r < 3; r++) {
        float v = xr[threadIdx.x + r * 256];
        vals[r] = v;
        s += v; q += v * v;
    }
#pragma unroll
    for (int o = 16; o; o >>= 1) {
        s += __shfl_xor_sync(~0u, s, o);
        q += __shfl_xor_sync(~0u, q, o);
    }
    __shared__ float ss[8], sq[8];
    int w = threadIdx.x >> 5, l = threadIdx.x & 31;
    if (l == 0) { ss[w] = s; sq[w] = q; }
    __syncthreads();
    if (threadIdx.x == 0) {
        float ts = 0.f, tq = 0.f;
        for (int i = 0; i < 8; i++) { ts += ss[i]; tq += sq[i]; }
        ss[0] = ts; sq[0] = tq;
    }
    __syncthreads();
    float mean = ss[0] / C;
    float var = sq[0] / C - mean * mean;
    float inv = rsqrtf(var + 1e-5f);
#pragma unroll
    for (int r = 0; r < 3; r++) {
        int c = threadIdx.x + r * 256;
        float v = (vals[r] - mean) * inv * g[c] + bta[c];
        __half a, b;
        splitS(v, a, b);
        y1[(size_t)row * C + c] = a;
        y2[(size_t)row * C + c] = b;
    }
}

__global__ void __launch_bounds__(256) ln_f32_kernel(const float* __restrict__ x,
                                                     const float* __restrict__ add,
                                                     const float* __restrict__ g,
                                                     const float* __restrict__ bta,
                                                     float* __restrict__ y, int C)
{
    int row = blockIdx.x;
    const float* xr = x + (size_t)row * C;
    const float* ar = add + (size_t)row * C;
    float vals[3];
    float s = 0.f, q = 0.f;
#pragma unroll
    for (int r = 0; r < 3; r++) {
        int c = threadIdx.x + r * 256;
        float v = xr[c] + ar[c];
        vals[r] = v;
        s += v; q += v * v;
    }
#pragma unroll
    for (int o = 16; o; o >>= 1) {
        s += __shfl_xor_sync(~0u, s, o);
        q += __shfl_xor_sync(~0u, q, o);
    }
    __shared__ float ss[8], sq[8];
    int w = threadIdx.x >> 5, l = threadIdx.x & 31;
    if (l == 0) { ss[w] = s; sq[w] = q; }
    __syncthreads();
    if (threadIdx.x == 0) {
        float ts = 0.f, tq = 0.f;
        for (int i = 0; i < 8; i++) { ts += ss[i]; tq += sq[i]; }
        ss[0] = ts; sq[0] = tq;
    }
    __syncthreads();
    float mean = ss[0] / C;
    float var = sq[0] / C - mean * mean;
    float inv = rsqrtf(var + 1e-5f);
#pragma unroll
    for (int r = 0; r < 3; r++) {
        int c = threadIdx.x + r * 256;
        y[(size_t)row * C + c] = (vals[r] - mean) * inv * g[c] + bta[c];
    }
}

__global__ void __launch_bounds__(256) attn_kernel(const float* __restrict__ qkv,
                                                   __half* __restrict__ o1,
                                                   __half* __restrict__ o2)
{
    __shared__ float sq_[FF][DHH], sk_[FF][DHH], sv_[FF][DHH];
    __shared__ float G[FF][FF];
    __shared__ float ctab[FF];
    __shared__ float sa[NF2];
    __shared__ float kt[FF];
    int bh = blockIdx.x;
    int b = bh >> 3, hh = bh & 7;
    int tid = threadIdx.x;
    const float* base = qkv + ((size_t)b * FF) * (3 * EE) + hh * DHH;
    for (int idx = tid; idx < FF * (DHH / 4); idx += 256) {
        int t = idx / (DHH / 4), dq = idx % (DHH / 4);
        size_t off = (size_t)t * (3 * EE) + dq * 4;
        float4 vq = *reinterpret_cast<const float4*>(base + off);
        float4 vk = *reinterpret_cast<const float4*>(base + off + EE);
        float4 vv = *reinterpret_cast<const float4*>(base + off + 2 * EE);
        int d = dq * 4;
        sq_[t][d] = vq.x; sq_[t][d + 1] = vq.y; sq_[t][d + 2] = vq.z; sq_[t][d + 3] = vq.w;
        sk_[t][d] = vk.x; sk_[t][d + 1] = vk.y; sk_[t][d + 2] = vk.z; sk_[t][d + 3] = vk.w;
        sv_[t][d] = vv.x; sv_[t][d + 1] = vv.y; sv_[t][d + 2] = vv.z; sv_[t][d + 3] = vv.w;
    }
    if (tid < FF) ctab[tid] = cospif(2.0f * (float)tid / 25.0f);
    __syncthreads();
    for (int e = tid; e < FF * FF; e += 256) {
        int t = e / FF, s2 = e % FF;
        float acc = 0.f;
#pragma unroll 8
        for (int d = 0; d < DHH; d++) acc = fmaf(sq_[t][d], sk_[s2][d], acc);
        G[t][s2] = acc;
    }
    __syncthreads();
    if (tid < NF2) {
        float acc = 0.f;
        for (int t = 0; t < FF; t++)
            for (int s2 = 0; s2 < FF; s2++)
                acc = fmaf(G[t][s2], ctab[(tid * (t - s2 + FF)) % FF], acc);
        sa[tid] = acc * 0.10206207261596575f;
    }
    __syncthreads();
    if (tid == 0) {
        float mx = sa[0];
        for (int f = 1; f < NF2; f++) mx = fmaxf(mx, sa[f]);
        float e_[NF2], sum = 0.f;
        for (int f = 0; f < NF2; f++) { e_[f] = expf(sa[f] - mx); sum += e_[f]; }
        float inv = 1.0f / sum;
        for (int f = 0; f < NF2; f++) sa[f] = e_[f] * inv;
    }
    __syncthreads();
    if (tid < FF) {
        float acc = sa[0];
        for (int f = 1; f < NF2; f++) acc = fmaf(2.0f * sa[f], ctab[(f * tid) % FF], acc);
        kt[tid] = acc * 0.04f;
    }
    __syncthreads();
    size_t obase = ((size_t)b * FF) * EE + hh * DHH;
    for (int idx = tid; idx < FF * DHH; idx += 256) {
        int t = idx / DHH, d = idx % DHH;
        float acc = 0.f;
#pragma unroll
        for (int s2 = 0; s2 < FF; s2++)
            acc = fmaf(kt[(t - s2 + FF) % FF], sv_[s2][d], acc);
        __half a, bb;
        splitS(acc, a, bb);
        o1[obase + (size_t)t * EE + d] = a;
        o2[obase + (size_t)t * EE + d] = bb;
    }
}

// mean over time, vectorized
__global__ void __launch_bounds__(192) mean_kernel(const float* __restrict__ h,
                                                   float* __restrict__ hm)
{
    int b = blockIdx.x;
    int cq = threadIdx.x;
    float4 acc = make_float4(0.f, 0.f, 0.f, 0.f);
    const float4* base = reinterpret_cast<const float4*>(h + (size_t)b * FF * EE) + cq;
#pragma unroll
    for (int f = 0; f < FF; f++) {
        float4 v = base[f * (EE / 4)];
        acc.x += v.x; acc.y += v.y; acc.z += v.z; acc.w += v.w;
    }
    acc.x *= 0.04f; acc.y *= 0.04f; acc.z *= 0.04f; acc.w *= 0.04f;
    reinterpret_cast<float4*>(hm + (size_t)b * EE)[cq] = acc;
}

// ---------------- host helpers ----------------
static inline void gemm_f32out(const __half* a1, const __half* a2,
                               const __half* b1, const __half* b2, float* C,
                               int M, int N, int K, const float* bias, const float* res, int act)
{
    dim3 grid(N / 128, M / 128);
    gemm_mma_kernel<<<grid, 256, G6_TOTAL>>>(a1, a2, b1, b2, C, nullptr, nullptr,
                                             M, N, K, bias, res, act);
}
static inline void gemm_splitout(const __half* a1, const __half* a2,
                                 const __half* b1, const __half* b2,
                                 __half* C1, __half* C2,
                                 int M, int N, int K, const float* bias, const float* res, int act)
{
    dim3 grid(N / 128, M / 128);
    gemm_mma_kernel<<<grid, 256, G6_TOTAL>>>(a1, a2, b1, b2, nullptr, C1, C2,
                                             M, N, K, bias, res, act);
}
static inline void tsplit(const float* W, __half* b1, __half* b2, int K, int N) {
    dim3 grid(N / 64, K / 64);
    tsplit_kernel<<<grid, 256>>>(W, b1, b2, K, N);
}

extern "C" void kernel_launch(void* const* d_in, const int* in_sizes, int n_in,
                              void* d_out, int out_size)
{
    const float* x       = (const float*)d_in[0];
    const float* W_in    = (const float*)d_in[1];
    const float* b_in    = (const float*)d_in[2];
    const float* pe      = (const float*)d_in[3];
    const float* W_shape = (const float*)d_in[4];
    const float* b_shape = (const float*)d_in[5];
    const float* W_patch = (const float*)d_in[6];
    const float* b_patch = (const float*)d_in[7];
    const float* cw1     = (const float*)d_in[8];
    const float* cb1     = (const float*)d_in[9];
    const float* cw2     = (const float*)d_in[10];
    const float* cb2     = (const float*)d_in[11];
    const float* cw4     = (const float*)d_in[12];
    const float* cb4     = (const float*)d_in[13];
    const float* ln1g    = (const float*)d_in[14];
    const float* ln1b    = (const float*)d_in[15];
    const float* Wqkv    = (const float*)d_in[16];
    const float* Wo      = (const float*)d_in[17];
    const float* bo      = (const float*)d_in[18];
    const float* ln2g    = (const float*)d_in[19];
    const float* ln2b    = (const float*)d_in[20];
    const float* Wf1     = (const float*)d_in[21];
    const float* bf1     = (const float*)d_in[22];
    const float* Wf2     = (const float*)d_in[23];
    const float* bf2     = (const float*)d_in[24];
    const float* ssmw    = (const float*)d_in[25];
    const float* ssmb    = (const float*)d_in[26];
    const float* ssmg    = (const float*)d_in[27];
    const float* ssmbn   = (const float*)d_in[28];
    const float* W_out   = (const float*)d_in[29];
    const float* b_out   = (const float*)d_in[30];
    float* out = (float*)d_out;

    cudaFuncSetAttribute(gemm_mma_kernel, cudaFuncAttributeMaxDynamicSharedMemorySize, G6_TOTAL);

    float *h1, *hpe, *hp, *fr, *C48, *cb, *h, *qkv, *s, *hm;
    cudaGetSymbolAddress((void**)&h1,  g_h1);
    cudaGetSymbolAddress((void**)&hpe, g_hpe);
    cudaGetSymbolAddress((void**)&hp,  g_hp);
    cudaGetSymbolAddress((void**)&fr,  g_fr);
    cudaGetSymbolAddress((void**)&C48, g_C48);
    cudaGetSymbolAddress((void**)&cb,  g_cb);
    cudaGetSymbolAddress((void**)&h,   g_h);
    cudaGetSymbolAddress((void**)&qkv, g_qkv);
    cudaGetSymbolAddress((void**)&s,   g_s);
    cudaGetSymbolAddress((void**)&hm,  g_hm);

    __half *xs1, *xs2, *sf1, *sf2, *h21, *h22, *col1, *col2, *y1, *y2, *att1, *att2, *mid1, *mid2;
    cudaGetSymbolAddress((void**)&xs1,  g_xs1);  cudaGetSymbolAddress((void**)&xs2,  g_xs2);
    cudaGetSymbolAddress((void**)&sf1,  g_sf1);  cudaGetSymbolAddress((void**)&sf2,  g_sf2);
    cudaGetSymbolAddress((void**)&h21,  g_h21);  cudaGetSymbolAddress((void**)&h22,  g_h22);
    cudaGetSymbolAddress((void**)&col1, g_col1); cudaGetSymbolAddress((void**)&col2, g_col2);
    cudaGetSymbolAddress((void**)&y1,   g_y1);   cudaGetSymbolAddress((void**)&y2,   g_y2);
    cudaGetSymbolAddress((void**)&att1, g_att1); cudaGetSymbolAddress((void**)&att2, g_att2);
    cudaGetSymbolAddress((void**)&mid1, g_mid1); cudaGetSymbolAddress((void**)&mid2, g_mid2);

    __half *tWin_h, *tWin_2, *tWsh_h, *tWsh_2, *tWpa_h, *tWpa_2, *tWc_h, *tWc_2;
    __half *tWqkv_h, *tWqkv_2, *tWo_h, *tWo_2, *tWf1_h, *tWf1_2, *tWf2_h, *tWf2_2, *tWc2_h, *tWc2_2;
    cudaGetSymbolAddress((void**)&tWin_h,  g_tWin_h);  cudaGetSymbolAddress((void**)&tWin_2,  g_tWin_2);
    cudaGetSymbolAddress((void**)&tWsh_h,  g_tWsh_h);  cudaGetSymbolAddress((void**)&tWsh_2,  g_tWsh_2);
    cudaGetSymbolAddress((void**)&tWpa_h,  g_tWpa_h);  cudaGetSymbolAddress((void**)&tWpa_2,  g_tWpa_2);
    cudaGetSymbolAddress((void**)&tWc_h,   g_tWc_h);   cudaGetSymbolAddress((void**)&tWc_2,   g_tWc_2);
    cudaGetSymbolAddress((void**)&tWqkv_h, g_tWqkv_h); cudaGetSymbolAddress((void**)&tWqkv_2, g_tWqkv_2);
    cudaGetSymbolAddress((void**)&tWo_h,   g_tWo_h);   cudaGetSymbolAddress((void**)&tWo_2,   g_tWo_2);
    cudaGetSymbolAddress((void**)&tWf1_h,  g_tWf1_h);  cudaGetSymbolAddress((void**)&tWf1_2,  g_tWf1_2);
    cudaGetSymbolAddress((void**)&tWf2_h,  g_tWf2_h);  cudaGetSymbolAddress((void**)&tWf2_2,  g_tWf2_2);
    cudaGetSymbolAddress((void**)&tWc2_h,  g_tWc2_h);  cudaGetSymbolAddress((void**)&tWc2_2,  g_tWc2_2);

    // tables + weight prep
    init_c48_kernel<<<1, 256>>>(C48);
    tsplit(W_in,    tWin_h, tWin_2,  64, 256);
    tsplit(W_shape, tWsh_h, tWsh_2, 256, 256);
    tsplit(W_patch, tWpa_h, tWpa_2, 512, 256);
    assemble_conv_wT<<<(768 * 256 + 255) / 256, 256>>>(cw1, cw2, cw4, cb1, cb2, cb4, tWc_h, tWc_2, cb);
    for (int i = 0; i < LL; i++) {
        tsplit(Wqkv + (size_t)i * EE * 3 * EE, tWqkv_h + (size_t)i * 3 * EE * EE, tWqkv_2 + (size_t)i * 3 * EE * EE, EE, 3 * EE);
        tsplit(Wo   + (size_t)i * EE * EE,     tWo_h   + (size_t)i * EE * EE,     tWo_2   + (size_t)i * EE * EE,     EE, EE);
        tsplit(Wf1  + (size_t)i * EE * 4 * EE, tWf1_h  + (size_t)i * 4 * EE * EE, tWf1_2  + (size_t)i * 4 * EE * EE, EE, 4 * EE);
        tsplit(Wf2  + (size_t)i * 4 * EE * EE, tWf2_h  + (size_t)i * EE * 4 * EE, tWf2_2  + (size_t)i * EE * 4 * EE, 4 * EE, EE);
    }
    assemble_ssm_wT<<<(768 * 576 + 255) / 256, 256>>>(ssmw, tWc2_h, tWc2_2);

    // embedding chain
    {
        size_t nq = N_BT * DIN / 4;
        split_x_kernel<<<(unsigned)((nq + 255) / 256), 256>>>(x, xs1, xs2, nq);
    }
    gemm_f32out(xs1, xs2, tWin_h, tWin_2, h1, BB * TT, HH, DIN, b_in, nullptr, 0);
    {
        size_t nq = N_BT * HH / 4;
        pe_diff_kernel<<<(unsigned)((nq + 255) / 256), 256>>>(h1, pe, hpe, sf1, sf2);
    }
    gemm_splitout(sf1, sf2, tWsh_h, tWsh_2, h21, h22, BB * TT, HH, HH, b_shape, hpe, 0);
    gemm_f32out(h21, h22, tWpa_h, tWpa_2, hp, BB * TP, HH, 2 * HH, b_patch, nullptr, 0);

    dft48_kernel<<<BB, 256>>>(hp, fr, C48);

    {
        size_t nq = N_BF * 256;
        im2col_conv<<<(unsigned)((nq + 255) / 256), 256>>>(fr, col1, col2);
    }
    gemm_f32out(col1, col2, tWc_h, tWc_2, h, (int)N_BF, EE, 1024, cb, nullptr, 0);

    // transformer layers
    for (int i = 0; i < LL; i++) {
        ln_kernel<<<(unsigned)N_BF, 256>>>(h, ln1g + (size_t)i * EE, ln1b + (size_t)i * EE, y1, y2, EE);
        gemm_f32out(y1, y2, tWqkv_h + (size_t)i * 3 * EE * EE, tWqkv_2 + (size_t)i * 3 * EE * EE,
                    qkv, (int)N_BF, 3 * EE, EE, nullptr, nullptr, 0);
        attn_kernel<<<BB * NHEADS, 256>>>(qkv, att1, att2);
        gemm_f32out(att1, att2, tWo_h + (size_t)i * EE * EE, tWo_2 + (size_t)i * EE * EE,
                    h, (int)N_BF, EE, EE, bo + (size_t)i * EE, h, 0);
        ln_kernel<<<(unsigned)N_BF, 256>>>(h, ln2g + (size_t)i * EE, ln2b + (size_t)i * EE, y1, y2, EE);
        gemm_splitout(y1, y2, tWf1_h + (size_t)i * 4 * EE * EE, tWf1_2 + (size_t)i * 4 * EE * EE,
                      mid1, mid2, (int)N_BF, 4 * EE, EE, bf1 + (size_t)i * 4 * EE, nullptr, 1);
        gemm_f32out(mid1, mid2, tWf2_h + (size_t)i * EE * 4 * EE, tWf2_2 + (size_t)i * EE * 4 * EE,
                    h, (int)N_BF, EE, 4 * EE, bf2 + (size_t)i * EE, h, 0);
    }

    // SSM conv + LN
    {
        size_t nq = N_BF * 576;
        im2col_ssm<<<(unsigned)((nq + 255) / 256), 256>>>(h, col1, col2);
    }
    gemm_f32out(col1, col2, tWc2_h, tWc2_2, s, (int)N_BF, EE, 3 * EE, ssmb, nullptr, 0);
    ln_f32_kernel<<<(unsigned)N_BF, 256>>>(h, s, ssmg, ssmbn, h, EE);

    // mean + classifier
    mean_kernel<<<BB, 192>>>(h, hm);
    {
        dim3 grid((NCC + 127) / 128, (BB + 127) / 128);
        sgemm_kernel<<<grid, 256>>>(hm, W_out, out, BB, NCC, EE, b_out);
    }
}

// round 16
// speedup vs baseline: 1.0079x; 1.0079x over previous
#include <cuda_runtime.h>
#include <cuda_fp16.h>
#include <math.h>
#include <stdint.h>

// ---------------- problem constants ----------------
#define BB    512
#define TT    96
#define DIN   64
#define HH    256
#define LL    4
#define EE    768
#define NCC   100
#define TP    48
#define FF    25
#define NF2   13
#define DHH   96
#define NHEADS 8

#define N_BT  ((size_t)BB * TT)   // 49152
#define N_BF  ((size_t)BB * FF)   // 12800

#define SPLIT_C63_64  0.984375f
#define FINAL_SCALE   0.9846153846153846f

// ---------------- scratch buffers ----------------
__device__ __align__(16) float g_h1 [N_BT * HH];
__device__ __align__(16) float g_hpe[N_BT * HH];
__device__ __align__(16) float g_hp [(size_t)BB * TP * HH];
__device__ __align__(16) float g_fr [N_BF * HH];
__device__ __align__(16) float g_C48[FF * TP];
__device__ __align__(16) float g_cb [EE];
__device__ __align__(16) float g_h  [N_BF * EE];
__device__ __align__(16) float g_qkv[N_BF * 3 * EE];
__device__ __align__(16) float g_s  [N_BF * EE];
__device__ __align__(16) float g_hm [(size_t)BB * EE];

// split-fp16 GEMM-A buffers
__device__ __align__(16) __half g_xs1 [N_BT * DIN],      g_xs2 [N_BT * DIN];
__device__ __align__(16) __half g_sf1 [N_BT * HH],       g_sf2 [N_BT * HH];
__device__ __align__(16) __half g_h21 [N_BT * HH],       g_h22 [N_BT * HH];
__device__ __align__(16) __half g_col1[N_BF * 2304],     g_col2[N_BF * 2304];
__device__ __align__(16) __half g_y1  [N_BF * EE],       g_y2  [N_BF * EE];
__device__ __align__(16) __half g_att1[N_BF * EE],       g_att2[N_BF * EE];
__device__ __align__(16) __half g_mid1[N_BF * 4 * EE],   g_mid2[N_BF * 4 * EE];

// transposed fp16 weights [N][K]
__device__ __align__(16) __half g_tWin_h [256 * 64],       g_tWin_2 [256 * 64];
__device__ __align__(16) __half g_tWsh_h [256 * 256],      g_tWsh_2 [256 * 256];
__device__ __align__(16) __half g_tWpa_h [256 * 512],      g_tWpa_2 [256 * 512];
__device__ __align__(16) __half g_tWc_h  [768 * 1024],     g_tWc_2  [768 * 1024];
__device__ __align__(16) __half g_tWqkv_h[LL * 2304 * 768],g_tWqkv_2[LL * 2304 * 768];
__device__ __align__(16) __half g_tWo_h  [LL * 768 * 768], g_tWo_2  [LL * 768 * 768];
__device__ __align__(16) __half g_tWf1_h [LL * 3072 * 768],g_tWf1_2 [LL * 3072 * 768];
__device__ __align__(16) __half g_tWf2_h [LL * 768 * 3072],g_tWf2_2 [LL * 768 * 3072];
__device__ __align__(16) __half g_tWc2_h [768 * 2304],     g_tWc2_2 [768 * 2304];

// ---------------- helpers ----------------
__device__ __forceinline__ uint32_t smem_u32(const void* p) {
    uint32_t a;
    asm("{ .reg .u64 t; cvta.to.shared.u64 t, %1; cvt.u32.u64 %0, t; }" : "=r"(a) : "l"(p));
    return a;
}
__device__ __forceinline__ uint32_t hpack(__half a, __half b) {
    __half2 t; t.x = a; t.y = b;
    return *reinterpret_cast<uint32_t*>(&t);
}

__device__ __forceinline__ void splitS(float a, __half& x1, __half& x2) {
    x1 = __float2half_rn(a);
    x2 = __float2half_rn(fmaf(-SPLIT_C63_64, __half2float(x1), a));
}
__device__ __forceinline__ void splitB(float w, __half& b1, __half& b2) {
    b1 = __float2half_rn(w);
    float b1f = __half2float(b1);
    b2 = __float2half_rn(fmaf(64.f, w - b1f, b1f));
}
__device__ __forceinline__ void splitS4(float4 v, uint2& o1, uint2& o2) {
    __half a0, b0, a1, b1, a2, b2, a3, b3;
    splitS(v.x, a0, b0); splitS(v.y, a1, b1);
    splitS(v.z, a2, b2); splitS(v.w, a3, b3);
    o1 = make_uint2(hpack(a0, a1), hpack(a2, a3));
    o2 = make_uint2(hpack(b0, b1), hpack(b2, b3));
}

#define SWZ128(x) ((x) ^ (((x) >> 3) & 0x70))

#define LDMX4(r, a) \
    asm volatile("ldmatrix.sync.aligned.m8n8.x4.shared.b16 {%0,%1,%2,%3}, [%4];" \
        : "=r"((r)[0]), "=r"((r)[1]), "=r"((r)[2]), "=r"((r)[3]) : "r"(a))
#define MMA16816(d, A, Bf) \
    asm volatile("mma.sync.aligned.m16n8k16.row.col.f32.f16.f16.f32 " \
        "{%0,%1,%2,%3}, {%4,%5,%6,%7}, {%8,%9}, {%0,%1,%2,%3};" \
        : "+f"((d)[0]), "+f"((d)[1]), "+f"((d)[2]), "+f"((d)[3]) \
        : "r"((A)[0]), "r"((A)[1]), "r"((A)[2]), "r"((A)[3]), "r"((Bf)[0]), "r"((Bf)[1]))

#define CP_ASYNC16(dst, src) \
    asm volatile("cp.async.cg.shared.global [%0], [%1], 16;" :: "r"(dst), "l"(src))
#define CP_COMMIT()  asm volatile("cp.async.commit_group;" ::: "memory")
#define CP_WAIT1()   asm volatile("cp.async.wait_group 1;" ::: "memory")

// ---------------- HMMA GEMM (R12 exact: two-pass epilogue) ----------------
#define G6_A      0
#define G6_B      16384
#define G6_STAGE  32768
#define G6_TOTAL  98304

__global__ void __launch_bounds__(256, 2)
gemm_mma_kernel(const __half* __restrict__ A1, const __half* __restrict__ A2,
                const __half* __restrict__ B1g, const __half* __restrict__ B2g,
                float* __restrict__ Cf, __half* __restrict__ C1, __half* __restrict__ C2,
                int M, int N, int K,
                const float* __restrict__ bias, const float* __restrict__ res, int act)
{
    extern __shared__ char smem[];
    const uint32_t sb = smem_u32(smem);
    const int tid  = threadIdx.x;
    const int lane = tid & 31;
    const int wid  = tid >> 5;
    const int wm   = wid & 1;
    const int wn   = wid >> 1;
    const int m0 = blockIdx.y * 128;
    const int n0 = blockIdx.x * 128;

    const int ldRow  = tid >> 1;
    const int ldHalf = tid & 1;

    float acc[4][4][4];
#pragma unroll
    for (int i = 0; i < 4; i++)
#pragma unroll
        for (int j = 0; j < 4; j++)
#pragma unroll
            for (int e = 0; e < 4; e++) acc[i][j][e] = 0.f;

    const int nk = K >> 5;

    const uint32_t aBase = (uint32_t)(wm * 64 + (lane & 15)) * 128u + (uint32_t)(lane >> 4) * 16u;
    const uint32_t bBase = (uint32_t)(wn * 32 + (lane >> 4) * 8 + (lane & 7)) * 128u
                         + (uint32_t)((lane >> 3) & 1) * 16u;

    auto issueStage = [&](int kc, uint32_t bufb) {
        const __half* A1p = A1 + (size_t)(m0 + ldRow) * K + kc * 32;
        const __half* A2p = A2 + (size_t)(m0 + ldRow) * K + kc * 32;
        const __half* B1p = B1g + (size_t)(n0 + ldRow) * K + kc * 32;
        const __half* B2p = B2g + (size_t)(n0 + ldRow) * K + kc * 32;
#pragma unroll
        for (int j = 0; j < 2; j++) {
            int c = ldHalf * 2 + j;
            uint32_t r1 = (uint32_t)ldRow * 128u + (uint32_t)c * 16u;
            CP_ASYNC16(sb + bufb + G6_A + SWZ128(r1),       A1p + c * 8);
            CP_ASYNC16(sb + bufb + G6_A + SWZ128(r1 + 64u), A2p + c * 8);
            CP_ASYNC16(sb + bufb + G6_B + SWZ128(r1),       B1p + c * 8);
            CP_ASYNC16(sb + bufb + G6_B + SWZ128(r1 + 64u), B2p + c * 8);
        }
    };

    issueStage(0, 0);
    CP_COMMIT();
    if (1 < nk) issueStage(1, G6_STAGE);
    CP_COMMIT();

    int stage = 0;
    for (int kc = 0; kc < nk; kc++) {
        CP_WAIT1();
        __syncthreads();
        if (kc + 2 < nk) {
            int ns = stage + 2; if (ns >= 3) ns -= 3;
            issueStage(kc + 2, (uint32_t)ns * G6_STAGE);
        }
        CP_COMMIT();
        const uint32_t bufo = (uint32_t)stage * G6_STAGE;
#pragma unroll
        for (int kk = 0; kk < 2; kk++) {
            const uint32_t kb = (uint32_t)kk * 32u;
            const uint32_t a1Sw = SWZ128(aBase + kb);
            const uint32_t a2Sw = SWZ128(aBase + kb + 64u);
            const uint32_t b1Sw = SWZ128(bBase + kb);
            const uint32_t b2Sw = SWZ128(bBase + kb + 64u);
            uint32_t b1f[2][4], b2f[2][4];
#pragma unroll
            for (int ni2 = 0; ni2 < 2; ni2++) {
                uint32_t b_addr = sb + bufo + G6_B + (uint32_t)(ni2 * 2048);
                LDMX4(b1f[ni2], b_addr + b1Sw);
                LDMX4(b2f[ni2], b_addr + b2Sw);
            }
#pragma unroll
            for (int mi = 0; mi < 4; mi++) {
                uint32_t x1f[4], x2f[4];
                uint32_t a_addr = sb + bufo + G6_A + (uint32_t)(mi * 2048);
                LDMX4(x1f, a_addr + a1Sw);
                LDMX4(x2f, a_addr + a2Sw);
#pragma unroll
                for (int ni = 0; ni < 4; ni++) {
                    MMA16816(acc[mi][ni], x1f, &b1f[ni >> 1][(ni & 1) * 2]);
                    MMA16816(acc[mi][ni], x2f, &b2f[ni >> 1][(ni & 1) * 2]);
                }
            }
        }
        if (++stage == 3) stage = 0;
    }
    __syncthreads();

    // R12 two-pass epilogue: 64 rows at a time (stride 132)
    float* stg = reinterpret_cast<float*>(smem);
#pragma unroll
    for (int half = 0; half < 2; half++) {
        __syncthreads();
        if (wm == half) {
#pragma unroll
            for (int mi = 0; mi < 4; mi++) {
#pragma unroll
                for (int ni = 0; ni < 4; ni++) {
                    int r = mi * 16 + (lane >> 2);
                    int c = wn * 32 + ni * 8 + (lane & 3) * 2;
                    stg[r * 132 + c]           = acc[mi][ni][0];
                    stg[r * 132 + c + 1]       = acc[mi][ni][1];
                    stg[(r + 8) * 132 + c]     = acc[mi][ni][2];
                    stg[(r + 8) * 132 + c + 1] = acc[mi][ni][3];
                }
            }
        }
        __syncthreads();
#pragma unroll 4
        for (int it = 0; it < 32; it++) {
            int idx = it * 256 + tid;
            int r = idx >> 7, c = idx & 127;
            float v = stg[r * 132 + c] * FINAL_SCALE;
            int gn = n0 + c;
            size_t gr = (size_t)(m0 + half * 64 + r);
            if (bias) v += bias[gn];
            if (res)  v += res[gr * N + gn];
            if (act)  v = 0.5f * v * (1.0f + erff(v * 0.70710678118654752f));
            if (C1) {
                __half o1, o2;
                splitS(v, o1, o2);
                C1[gr * N + gn] = o1;
                C2[gr * N + gn] = o2;
            } else {
                Cf[gr * N + gn] = v;
            }
        }
    }
}

// ---------------- fallback f32 SGEMM (classifier only) ----------------
__global__ void __launch_bounds__(256, 2)
sgemm_kernel(const float* __restrict__ A, const float* __restrict__ B,
             float* __restrict__ C, int M, int N, int K,
             const float* __restrict__ bias)
{
    __shared__ float As[8][128];
    __shared__ float Bs[8][128];
    const int tid = threadIdx.x;
    const int row0 = blockIdx.y * 128, col0 = blockIdx.x * 128;
    const int tx = tid & 15, ty = tid >> 4;
    const int arow = tid >> 1, acol = (tid & 1) * 4;
    const int brow = tid >> 5, bcol = (tid & 31) * 4;
    float acc[8][8];
#pragma unroll
    for (int i = 0; i < 8; i++)
#pragma unroll
        for (int j = 0; j < 8; j++) acc[i][j] = 0.f;
    const int gar = row0 + arow, gbc = col0 + bcol;
    const bool aok = (gar < M), bok = (gbc < N);
    for (int k0 = 0; k0 < K; k0 += 8) {
        float4 avv = make_float4(0, 0, 0, 0);
        if (aok) avv = *reinterpret_cast<const float4*>(&A[(size_t)gar * K + k0 + acol]);
        As[acol + 0][arow] = avv.x; As[acol + 1][arow] = avv.y;
        As[acol + 2][arow] = avv.z; As[acol + 3][arow] = avv.w;
        float4 bv = make_float4(0, 0, 0, 0);
        if (bok) bv = *reinterpret_cast<const float4*>(&B[(size_t)(k0 + brow) * N + gbc]);
        *reinterpret_cast<float4*>(&Bs[brow][bcol]) = bv;
        __syncthreads();
#pragma unroll
        for (int kk = 0; kk < 8; kk++) {
            float4 ra0 = *reinterpret_cast<const float4*>(&As[kk][ty * 8 + 0]);
            float4 ra1 = *reinterpret_cast<const float4*>(&As[kk][ty * 8 + 4]);
            float4 rb0 = *reinterpret_cast<const float4*>(&Bs[kk][tx * 8 + 0]);
            float4 rb1 = *reinterpret_cast<const float4*>(&Bs[kk][tx * 8 + 4]);
            float ra[8] = {ra0.x, ra0.y, ra0.z, ra0.w, ra1.x, ra1.y, ra1.z, ra1.w};
            float rb[8] = {rb0.x, rb0.y, rb0.z, rb0.w, rb1.x, rb1.y, rb1.z, rb1.w};
#pragma unroll
            for (int i = 0; i < 8; i++)
#pragma unroll
                for (int j = 0; j < 8; j++) acc[i][j] = fmaf(ra[i], rb[j], acc[i][j]);
        }
        __syncthreads();
    }
#pragma unroll
    for (int i = 0; i < 8; i++) {
        const int r = row0 + ty * 8 + i;
        if (r >= M) continue;
#pragma unroll
        for (int j = 0; j < 8; j++) {
            const int c = col0 + tx * 8 + j;
            if (c >= N) continue;
            float v = acc[i][j];
            if (bias) v += bias[c];
            C[(size_t)r * N + c] = v;
        }
    }
}

// ---------------- weight transpose + split: 64x64 tiles, layer-batched via blockIdx.z ----------------
__global__ void __launch_bounds__(256) tsplit_kernel(const float* __restrict__ W,
                                                     __half* __restrict__ b1,
                                                     __half* __restrict__ b2, int K, int N)
{
    const size_t mStride = (size_t)K * N * blockIdx.z;
    const float* Wl = W + mStride;
    __half* b1l = b1 + mStride;
    __half* b2l = b2 + mStride;

    __shared__ float t[64][65];
    const int k0 = blockIdx.y * 64, n0 = blockIdx.x * 64;
    const int tid = threadIdx.x;
    const int tx = tid & 15, ty = tid >> 4;
#pragma unroll
    for (int r = 0; r < 4; r++) {
        int kl = ty + r * 16;
        float4 v = *reinterpret_cast<const float4*>(&Wl[(size_t)(k0 + kl) * N + n0 + tx * 4]);
        t[kl][tx * 4 + 0] = v.x;
        t[kl][tx * 4 + 1] = v.y;
        t[kl][tx * 4 + 2] = v.z;
        t[kl][tx * 4 + 3] = v.w;
    }
    __syncthreads();
    const int kq = tid & 15, nr = tid >> 4;
#pragma unroll
    for (int r = 0; r < 4; r++) {
        int nl = nr + r * 16;
        __half h1[4], h2[4];
#pragma unroll
        for (int j = 0; j < 4; j++)
            splitB(t[kq * 4 + j][nl], h1[j], h2[j]);
        size_t off = (size_t)(n0 + nl) * K + k0 + kq * 4;
        *reinterpret_cast<uint2*>(&b1l[off]) = make_uint2(hpack(h1[0], h1[1]), hpack(h1[2], h1[3]));
        *reinterpret_cast<uint2*>(&b2l[off]) = make_uint2(hpack(h2[0], h2[1]), hpack(h2[2], h2[3]));
    }
}

__global__ void assemble_conv_wT(const float* __restrict__ w1, const float* __restrict__ w2,
                                 const float* __restrict__ w4, const float* __restrict__ b1c,
                                 const float* __restrict__ b2c, const float* __restrict__ b4c,
                                 __half* __restrict__ o1, __half* __restrict__ o2,
                                 float* __restrict__ cb)
{
    int q = blockIdx.x * blockDim.x + threadIdx.x;
    if (q < EE) cb[q] = (q < 256) ? b1c[q] : (q < 512 ? b2c[q - 256] : b4c[q - 512]);
    if (q >= 768 * 256) return;
    int n = q >> 8, kq = q & 255;
    int d = kq >> 6;
    int i = (kq & 63) * 4;
    float v[4] = {0.f, 0.f, 0.f, 0.f};
    if (n < 256) {
        if (d == 1) {
            float4 t = *reinterpret_cast<const float4*>(&w1[n * 256 + i]);
            v[0] = t.x; v[1] = t.y; v[2] = t.z; v[3] = t.w;
        }
    } else if (n < 512) {
        int oo = n - 256, j = d - 1;
        if (j == 0 || j == 1)
#pragma unroll
            for (int e = 0; e < 4; e++) v[e] = w2[oo * 512 + (i + e) * 2 + j];
    } else {
        int oo = n - 512;
#pragma unroll
        for (int e = 0; e < 4; e++) v[e] = w4[oo * 1024 + (i + e) * 4 + d];
    }
    __half h1[4], h2[4];
#pragma unroll
    for (int e = 0; e < 4; e++) splitB(v[e], h1[e], h2[e]);
    size_t off = (size_t)q * 4;
    *reinterpret_cast<uint2*>(&o1[off]) = make_uint2(hpack(h1[0], h1[1]), hpack(h1[2], h1[3]));
    *reinterpret_cast<uint2*>(&o2[off]) = make_uint2(hpack(h2[0], h2[1]), hpack(h2[2], h2[3]));
}

__global__ void assemble_ssm_wT(const float* __restrict__ w, __half* __restrict__ o1,
                                __half* __restrict__ o2)
{
    int q = blockIdx.x * blockDim.x + threadIdx.x;
    if (q >= 768 * 576) return;
    int n = q / 576, kq = q % 576;
    int j = kq / 192;
    int i = (kq % 192) * 4;
    __half h1[4], h2[4];
#pragma unroll
    for (int e = 0; e < 4; e++)
        splitB(w[(size_t)n * 2304 + (i + e) * 3 + j], h1[e], h2[e]);
    size_t off = (size_t)q * 4;
    *reinterpret_cast<uint2*>(&o1[off]) = make_uint2(hpack(h1[0], h1[1]), hpack(h1[2], h1[3]));
    *reinterpret_cast<uint2*>(&o2[off]) = make_uint2(hpack(h2[0], h2[1]), hpack(h2[2], h2[3]));
}

// ---------------- small kernels ----------------
__global__ void init_c48_kernel(float* __restrict__ C48) {
    for (int i = threadIdx.x; i < FF * TP; i += blockDim.x) {
        int k = i / TP, t = i % TP;
        int m = (k * t) % TP;
        C48[i] = cospif(2.0f * (float)m / (float)TP);
    }
}

__global__ void split_x_kernel(const float* __restrict__ x, __half* __restrict__ x1,
                               __half* __restrict__ x2, size_t nquads)
{
    size_t q = (size_t)blockIdx.x * blockDim.x + threadIdx.x;
    if (q >= nquads) return;
    float4 v = reinterpret_cast<const float4*>(x)[q];
    uint2 o1, o2;
    splitS4(v, o1, o2);
    reinterpret_cast<uint2*>(x1)[q] = o1;
    reinterpret_cast<uint2*>(x2)[q] = o2;
}

__global__ void pe_diff_kernel(const float* __restrict__ h1, const float* __restrict__ pe,
                               float* __restrict__ hpe, __half* __restrict__ sf1,
                               __half* __restrict__ sf2)
{
    size_t q = (size_t)blockIdx.x * blockDim.x + threadIdx.x;
    const size_t nquads = N_BT * HH / 4;
    if (q >= nquads) return;
    int cq = (int)(q % (HH / 4));
    size_t r = q / (HH / 4);
    int t = (int)(r % TT);
    float4 hv = reinterpret_cast<const float4*>(h1)[q];
    float4 pv = reinterpret_cast<const float4*>(pe)[(size_t)t * (HH / 4) + cq];
    float4 cur = make_float4(hv.x + pv.x, hv.y + pv.y, hv.z + pv.z, hv.w + pv.w);
    reinterpret_cast<float4*>(hpe)[q] = cur;
    float4 prev;
    if (t == 0) {
        prev = cur;
    } else {
        float4 hv0 = reinterpret_cast<const float4*>(h1)[q - HH / 4];
        float4 pv0 = reinterpret_cast<const float4*>(pe)[(size_t)(t - 1) * (HH / 4) + cq];
        prev = make_float4(hv0.x + pv0.x, hv0.y + pv0.y, hv0.z + pv0.z, hv0.w + pv0.w);
    }
    float4 d = make_float4(cur.x - prev.x, cur.y - prev.y, cur.z - prev.z, cur.w - prev.w);
    uint2 o1, o2;
    splitS4(d, o1, o2);
    reinterpret_cast<uint2*>(sf1)[q] = o1;
    reinterpret_cast<uint2*>(sf2)[q] = o2;
}

__global__ void __launch_bounds__(256) dft48_kernel(const float* __restrict__ hp,
                                                    float* __restrict__ out,
                                                    const float* __restrict__ C48)
{
    __shared__ float sC[FF * TP];
    int b = blockIdx.x;
    for (int i = threadIdx.x; i < FF * TP; i += 256) sC[i] = C48[i];
    float r[TP];
    const float* base = hp + (size_t)b * TP * HH + threadIdx.x;
#pragma unroll
    for (int t = 0; t < TP; t++) r[t] = base[(size_t)t * HH];
    __syncthreads();
    float* ob = out + (size_t)b * FF * HH + threadIdx.x;
    for (int k = 0; k < FF; k++) {
        float acc = 0.f;
#pragma unroll
        for (int t = 0; t < TP; t++) acc = fmaf(r[t], sC[k * TP + t], acc);
        ob[(size_t)k * HH] = acc;
    }
}

__global__ void im2col_conv(const float* __restrict__ f, __half* __restrict__ c1,
                            __half* __restrict__ c2)
{
    size_t q = (size_t)blockIdx.x * blockDim.x + threadIdx.x;
    const size_t nquads = N_BF * 256;
    if (q >= nquads) return;
    int kq = (int)(q % 256);
    size_t row = q / 256;
    int d = kq / 64;
    int i = (kq % 64) * 4;
    int fq = (int)(row % FF);
    size_t b = row / FF;
    int src = fq + d - 1;
    float4 v = make_float4(0.f, 0.f, 0.f, 0.f);
    if (src >= 0 && src < FF)
        v = *reinterpret_cast<const float4*>(&f[((size_t)b * FF + src) * HH + i]);
    uint2 o1, o2;
    splitS4(v, o1, o2);
    reinterpret_cast<uint2*>(c1)[q] = o1;
    reinterpret_cast<uint2*>(c2)[q] = o2;
}

__global__ void im2col_ssm(const float* __restrict__ h, __half* __restrict__ c1,
                           __half* __restrict__ c2)
{
    size_t q = (size_t)blockIdx.x * blockDim.x + threadIdx.x;
    const size_t nquads = N_BF * 576;
    if (q >= nquads) return;
    int kq = (int)(q % 576);
    size_t row = q / 576;
    int j = kq / 192;
    int i = (kq % 192) * 4;
    int fq = (int)(row % FF);
    size_t b = row / FF;
    int src = fq + j - 1;
    float4 v = make_float4(0.f, 0.f, 0.f, 0.f);
    if (src >= 0 && src < FF)
        v = *reinterpret_cast<const float4*>(&h[((size_t)b * FF + src) * EE + i]);
    uint2 o1, o2;
    splitS4(v, o1, o2);
    reinterpret_cast<uint2*>(c1)[q] = o1;
    reinterpret_cast<uint2*>(c2)[q] = o2;
}

__global__ void __launch_bounds__(256) ln_kernel(const float* __restrict__ x,
                                                 const float* __restrict__ g,
                                                 const float* __restrict__ bta,
                                                 __half* __restrict__ y1,
                                                 __half* __restrict__ y2, int C)
{
    int row = blockIdx.x;
    const float* xr = x + (size_t)row * C;
    float vals[3];
    float s = 0.f, q = 0.f;
#pragma unroll
    for (int r = 0; r < 3; r++) {
        float v = xr[threadIdx.x + r * 256];
        vals[r] = v;
        s += v; q += v * v;
    }
#pragma unroll
    for (int o = 16; o; o >>= 1) {
        s += __shfl_xor_sync(~0u, s, o);
        q += __shfl_xor_sync(~0u, q, o);
    }
    __shared__ float ss[8], sq[8];
    int w = threadIdx.x >> 5, l = threadIdx.x & 31;
    if (l == 0) { ss[w] = s; sq[w] = q; }
    __syncthreads();
    if (threadIdx.x == 0) {
        float ts = 0.f, tq = 0.f;
        for (int i = 0; i < 8; i++) { ts += ss[i]; tq += sq[i]; }
        ss[0] = ts; sq[0] = tq;
    }
    __syncthreads();
    float mean = ss[0] / C;
    float var = sq[0] / C - mean * mean;
    float inv = rsqrtf(var + 1e-5f);
#pragma unroll
    for (int r = 0; r < 3; r++) {
        int c = threadIdx.x + r * 256;
        float v = (vals[r] - mean) * inv * g[c] + bta[c];
        __half a, b;
        splitS(v, a, b);
        y1[(size_t)row * C + c] = a;
        y2[(size_t)row * C + c] = b;
    }
}

__global__ void __launch_bounds__(256) ln_f32_kernel(const float* __restrict__ x,
                                                     const float* __restrict__ add,
                                                     const float* __restrict__ g,
                                                     const float* __restrict__ bta,
                                                     float* __restrict__ y, int C)
{
    int row = blockIdx.x;
    const float* xr = x + (size_t)row * C;
    const float* ar = add + (size_t)row * C;
    float vals[3];
    float s = 0.f, q = 0.f;
#pragma unroll
    for (int r = 0; r < 3; r++) {
        int c = threadIdx.x + r * 256;
        float v = xr[c] + ar[c];
        vals[r] = v;
        s += v; q += v * v;
    }
#pragma unroll
    for (int o = 16; o; o >>= 1) {
        s += __shfl_xor_sync(~0u, s, o);
        q += __shfl_xor_sync(~0u, q, o);
    }
    __shared__ float ss[8], sq[8];
    int w = threadIdx.x >> 5, l = threadIdx.x & 31;
    if (l == 0) { ss[w] = s; sq[w] = q; }
    __syncthreads();
    if (threadIdx.x == 0) {
        float ts = 0.f, tq = 0.f;
        for (int i = 0; i < 8; i++) { ts += ss[i]; tq += sq[i]; }
        ss[0] = ts; sq[0] = tq;
    }
    __syncthreads();
    float mean = ss[0] / C;
    float var = sq[0] / C - mean * mean;
    float inv = rsqrtf(var + 1e-5f);
#pragma unroll
    for (int r = 0; r < 3; r++) {
        int c = threadIdx.x + r * 256;
        y[(size_t)row * C + c] = (vals[r] - mean) * inv * g[c] + bta[c];
    }
}

__global__ void __launch_bounds__(256) attn_kernel(const float* __restrict__ qkv,
                                                   __half* __restrict__ o1,
                                                   __half* __restrict__ o2)
{
    __shared__ float sq_[FF][DHH], sk_[FF][DHH], sv_[FF][DHH];
    __shared__ float G[FF][FF];
    __shared__ float ctab[FF];
    __shared__ float sa[NF2];
    __shared__ float kt[FF];
    int bh = blockIdx.x;
    int b = bh >> 3, hh = bh & 7;
    int tid = threadIdx.x;
    const float* base = qkv + ((size_t)b * FF) * (3 * EE) + hh * DHH;
    for (int idx = tid; idx < FF * (DHH / 4); idx += 256) {
        int t = idx / (DHH / 4), dq = idx % (DHH / 4);
        size_t off = (size_t)t * (3 * EE) + dq * 4;
        float4 vq = *reinterpret_cast<const float4*>(base + off);
        float4 vk = *reinterpret_cast<const float4*>(base + off + EE);
        float4 vv = *reinterpret_cast<const float4*>(base + off + 2 * EE);
        int d = dq * 4;
        sq_[t][d] = vq.x; sq_[t][d + 1] = vq.y; sq_[t][d + 2] = vq.z; sq_[t][d + 3] = vq.w;
        sk_[t][d] = vk.x; sk_[t][d + 1] = vk.y; sk_[t][d + 2] = vk.z; sk_[t][d + 3] = vk.w;
        sv_[t][d] = vv.x; sv_[t][d + 1] = vv.y; sv_[t][d + 2] = vv.z; sv_[t][d + 3] = vv.w;
    }
    if (tid < FF) ctab[tid] = cospif(2.0f * (float)tid / 25.0f);
    __syncthreads();
    for (int e = tid; e < FF * FF; e += 256) {
        int t = e / FF, s2 = e % FF;
        float acc = 0.f;
#pragma unroll 8
        for (int d = 0; d < DHH; d++) acc = fmaf(sq_[t][d], sk_[s2][d], acc);
        G[t][s2] = acc;
    }
    __syncthreads();
    if (tid < NF2) {
        float acc = 0.f;
        for (int t = 0; t < FF; t++)
            for (int s2 = 0; s2 < FF; s2++)
                acc = fmaf(G[t][s2], ctab[(tid * (t - s2 + FF)) % FF], acc);
        sa[tid] = acc * 0.10206207261596575f;
    }
    __syncthreads();
    if (tid == 0) {
        float mx = sa[0];
        for (int f = 1; f < NF2; f++) mx = fmaxf(mx, sa[f]);
        float e_[NF2], sum = 0.f;
        for (int f = 0; f < NF2; f++) { e_[f] = expf(sa[f] - mx); sum += e_[f]; }
        float inv = 1.0f / sum;
        for (int f = 0; f < NF2; f++) sa[f] = e_[f] * inv;
    }
    __syncthreads();
    if (tid < FF) {
        float acc = sa[0];
        for (int f = 1; f < NF2; f++) acc = fmaf(2.0f * sa[f], ctab[(f * tid) % FF], acc);
        kt[tid] = acc * 0.04f;
    }
    __syncthreads();
    size_t obase = ((size_t)b * FF) * EE + hh * DHH;
    for (int idx = tid; idx < FF * DHH; idx += 256) {
        int t = idx / DHH, d = idx % DHH;
        float acc = 0.f;
#pragma unroll
        for (int s2 = 0; s2 < FF; s2++)
            acc = fmaf(kt[(t - s2 + FF) % FF], sv_[s2][d], acc);
        __half a, bb;
        splitS(acc, a, bb);
        o1[obase + (size_t)t * EE + d] = a;
        o2[obase + (size_t)t * EE + d] = bb;
    }
}

// mean over time (R12 scalar form)
__global__ void mean_kernel(const float* __restrict__ h, float* __restrict__ hm) {
    int b = blockIdx.x;
    int c = threadIdx.x;
    float acc = 0.f;
#pragma unroll
    for (int f = 0; f < FF; f++) acc += h[((size_t)b * FF + f) * EE + c];
    hm[(size_t)b * EE + c] = acc * 0.04f;
}

// ---------------- host helpers ----------------
static inline void gemm_f32out(const __half* a1, const __half* a2,
                               const __half* b1, const __half* b2, float* C,
                               int M, int N, int K, const float* bias, const float* res, int act)
{
    dim3 grid(N / 128, M / 128);
    gemm_mma_kernel<<<grid, 256, G6_TOTAL>>>(a1, a2, b1, b2, C, nullptr, nullptr,
                                             M, N, K, bias, res, act);
}
static inline void gemm_splitout(const __half* a1, const __half* a2,
                                 const __half* b1, const __half* b2,
                                 __half* C1, __half* C2,
                                 int M, int N, int K, const float* bias, const float* res, int act)
{
    gemm_mma_kernel<<<dim3(N / 128, M / 128), 256, G6_TOTAL>>>(a1, a2, b1, b2, nullptr, C1, C2,
                                                               M, N, K, bias, res, act);
}
static inline void tsplitL(const float* W, __half* b1, __half* b2, int K, int N, int L) {
    dim3 grid(N / 64, K / 64, L);
    tsplit_kernel<<<grid, 256>>>(W, b1, b2, K, N);
}

extern "C" void kernel_launch(void* const* d_in, const int* in_sizes, int n_in,
                              void* d_out, int out_size)
{
    const float* x       = (const float*)d_in[0];
    const float* W_in    = (const float*)d_in[1];
    const float* b_in    = (const float*)d_in[2];
    const float* pe      = (const float*)d_in[3];
    const float* W_shape = (const float*)d_in[4];
    const float* b_shape = (const float*)d_in[5];
    const float* W_patch = (const float*)d_in[6];
    const float* b_patch = (const float*)d_in[7];
    const float* cw1     = (const float*)d_in[8];
    const float* cb1     = (const float*)d_in[9];
    const float* cw2     = (const float*)d_in[10];
    const float* cb2     = (const float*)d_in[11];
    const float* cw4     = (const float*)d_in[12];
    const float* cb4     = (const float*)d_in[13];
    const float* ln1g    = (const float*)d_in[14];
    const float* ln1b    = (const float*)d_in[15];
    const float* Wqkv    = (const float*)d_in[16];
    const float* Wo      = (const float*)d_in[17];
    const float* bo      = (const float*)d_in[18];
    const float* ln2g    = (const float*)d_in[19];
    const float* ln2b    = (const float*)d_in[20];
    const float* Wf1     = (const float*)d_in[21];
    const float* bf1     = (const float*)d_in[22];
    const float* Wf2     = (const float*)d_in[23];
    const float* bf2     = (const float*)d_in[24];
    const float* ssmw    = (const float*)d_in[25];
    const float* ssmb    = (const float*)d_in[26];
    const float* ssmg    = (const float*)d_in[27];
    const float* ssmbn   = (const float*)d_in[28];
    const float* W_out   = (const float*)d_in[29];
    const float* b_out   = (const float*)d_in[30];
    float* out = (float*)d_out;

    cudaFuncSetAttribute(gemm_mma_kernel, cudaFuncAttributeMaxDynamicSharedMemorySize, G6_TOTAL);

    float *h1, *hpe, *hp, *fr, *C48, *cb, *h, *qkv, *s, *hm;
    cudaGetSymbolAddress((void**)&h1,  g_h1);
    cudaGetSymbolAddress((void**)&hpe, g_hpe);
    cudaGetSymbolAddress((void**)&hp,  g_hp);
    cudaGetSymbolAddress((void**)&fr,  g_fr);
    cudaGetSymbolAddress((void**)&C48, g_C48);
    cudaGetSymbolAddress((void**)&cb,  g_cb);
    cudaGetSymbolAddress((void**)&h,   g_h);
    cudaGetSymbolAddress((void**)&qkv, g_qkv);
    cudaGetSymbolAddress((void**)&s,   g_s);
    cudaGetSymbolAddress((void**)&hm,  g_hm);

    __half *xs1, *xs2, *sf1, *sf2, *h21, *h22, *col1, *col2, *y1, *y2, *att1, *att2, *mid1, *mid2;
    cudaGetSymbolAddress((void**)&xs1,  g_xs1);  cudaGetSymbolAddress((void**)&xs2,  g_xs2);
    cudaGetSymbolAddress((void**)&sf1,  g_sf1);  cudaGetSymbolAddress((void**)&sf2,  g_sf2);
    cudaGetSymbolAddress((void**)&h21,  g_h21);  cudaGetSymbolAddress((void**)&h22,  g_h22);
    cudaGetSymbolAddress((void**)&col1, g_col1); cudaGetSymbolAddress((void**)&col2, g_col2);
    cudaGetSymbolAddress((void**)&y1,   g_y1);   cudaGetSymbolAddress((void**)&y2,   g_y2);
    cudaGetSymbolAddress((void**)&att1, g_att1); cudaGetSymbolAddress((void**)&att2, g_att2);
    cudaGetSymbolAddress((void**)&mid1, g_mid1); cudaGetSymbolAddress((void**)&mid2, g_mid2);

    __half *tWin_h, *tWin_2, *tWsh_h, *tWsh_2, *tWpa_h, *tWpa_2, *tWc_h, *tWc_2;
    __half *tWqkv_h, *tWqkv_2, *tWo_h, *tWo_2, *tWf1_h, *tWf1_2, *tWf2_h, *tWf2_2, *tWc2_h, *tWc2_2;
    cudaGetSymbolAddress((void**)&tWin_h,  g_tWin_h);  cudaGetSymbolAddress((void**)&tWin_2,  g_tWin_2);
    cudaGetSymbolAddress((void**)&tWsh_h,  g_tWsh_h);  cudaGetSymbolAddress((void**)&tWsh_2,  g_tWsh_2);
    cudaGetSymbolAddress((void**)&tWpa_h,  g_tWpa_h);  cudaGetSymbolAddress((void**)&tWpa_2,  g_tWpa_2);
    cudaGetSymbolAddress((void**)&tWc_h,   g_tWc_h);   cudaGetSymbolAddress((void**)&tWc_2,   g_tWc_2);
    cudaGetSymbolAddress((void**)&tWqkv_h, g_tWqkv_h); cudaGetSymbolAddress((void**)&tWqkv_2, g_tWqkv_2);
    cudaGetSymbolAddress((void**)&tWo_h,   g_tWo_h);   cudaGetSymbolAddress((void**)&tWo_2,   g_tWo_2);
    cudaGetSymbolAddress((void**)&tWf1_h,  g_tWf1_h);  cudaGetSymbolAddress((void**)&tWf1_2,  g_tWf1_2);
    cudaGetSymbolAddress((void**)&tWf2_h,  g_tWf2_h);  cudaGetSymbolAddress((void**)&tWf2_2,  g_tWf2_2);
    cudaGetSymbolAddress((void**)&tWc2_h,  g_tWc2_h);  cudaGetSymbolAddress((void**)&tWc2_2,  g_tWc2_2);

    // tables + weight prep (per-layer families batched via gridDim.z)
    init_c48_kernel<<<1, 256>>>(C48);
    tsplitL(W_in,    tWin_h, tWin_2,  64, 256, 1);
    tsplitL(W_shape, tWsh_h, tWsh_2, 256, 256, 1);
    tsplitL(W_patch, tWpa_h, tWpa_2, 512, 256, 1);
    assemble_conv_wT<<<(768 * 256 + 255) / 256, 256>>>(cw1, cw2, cw4, cb1, cb2, cb4, tWc_h, tWc_2, cb);
    tsplitL(Wqkv, tWqkv_h, tWqkv_2, EE, 3 * EE, LL);
    tsplitL(Wo,   tWo_h,   tWo_2,   EE, EE,     LL);
    tsplitL(Wf1,  tWf1_h,  tWf1_2,  EE, 4 * EE, LL);
    tsplitL(Wf2,  tWf2_h,  tWf2_2,  4 * EE, EE, LL);
    assemble_ssm_wT<<<(768 * 576 + 255) / 256, 256>>>(ssmw, tWc2_h, tWc2_2);

    // embedding chain
    {
        size_t nq = N_BT * DIN / 4;
        split_x_kernel<<<(unsigned)((nq + 255) / 256), 256>>>(x, xs1, xs2, nq);
    }
    gemm_f32out(xs1, xs2, tWin_h, tWin_2, h1, BB * TT, HH, DIN, b_in, nullptr, 0);
    {
        size_t nq = N_BT * HH / 4;
        pe_diff_kernel<<<(unsigned)((nq + 255) / 256), 256>>>(h1, pe, hpe, sf1, sf2);
    }
    gemm_splitout(sf1, sf2, tWsh_h, tWsh_2, h21, h22, BB * TT, HH, HH, b_shape, hpe, 0);
    gemm_f32out(h21, h22, tWpa_h, tWpa_2, hp, BB * TP, HH, 2 * HH, b_patch, nullptr, 0);

    dft48_kernel<<<BB, 256>>>(hp, fr, C48);

    {
        size_t nq = N_BF * 256;
        im2col_conv<<<(unsigned)((nq + 255) / 256), 256>>>(fr, col1, col2);
    }
    gemm_f32out(col1, col2, tWc_h, tWc_2, h, (int)N_BF, EE, 1024, cb, nullptr, 0);

    // transformer layers
    for (int i = 0; i < LL; i++) {
        ln_kernel<<<(unsigned)N_BF, 256>>>(h, ln1g + (size_t)i * EE, ln1b + (size_t)i * EE, y1, y2, EE);
        gemm_f32out(y1, y2, tWqkv_h + (size_t)i * 3 * EE * EE, tWqkv_2 + (size_t)i * 3 * EE * EE,
                    qkv, (int)N_BF, 3 * EE, EE, nullptr, nullptr, 0);
        attn_kernel<<<BB * NHEADS, 256>>>(qkv, att1, att2);
        gemm_f32out(att1, att2, tWo_h + (size_t)i * EE * EE, tWo_2 + (size_t)i * EE * EE,
                    h, (int)N_BF, EE, EE, bo + (size_t)i * EE, h, 0);
        ln_kernel<<<(unsigned)N_BF, 256>>>(h, ln2g + (size_t)i * EE, ln2b + (size_t)i * EE, y1, y2, EE);
        gemm_splitout(y1, y2, tWf1_h + (size_t)i * 4 * EE * EE, tWf1_2 + (size_t)i * 4 * EE * EE,
                      mid1, mid2, (int)N_BF, 4 * EE, EE, bf1 + (size_t)i * 4 * EE, nullptr, 1);
        gemm_f32out(mid1, mid2, tWf2_h + (size_t)i * EE * 4 * EE, tWf2_2 + (size_t)i * EE * 4 * EE,
                    h, (int)N_BF, EE, 4 * EE, bf2 + (size_t)i * EE, h, 0);
    }

    // SSM conv + LN
    {
        size_t nq = N_BF * 576;
        im2col_ssm<<<(unsigned)((nq + 255) / 256), 256>>>(h, col1, col2);
    }
    gemm_f32out(col1, col2, tWc2_h, tWc2_2, s, (int)N_BF, EE, 3 * EE, ssmb, nullptr, 0);
    ln_f32_kernel<<<(unsigned)N_BF, 256>>>(h, s, ssmg, ssmbn, h, EE);

    // mean + classifier
    mean_kernel<<<BB, EE>>>(h, hm);
    {
        dim3 grid((NCC + 127) / 128, (BB + 127) / 128);
        sgemm_kernel<<<grid, 256>>>(hm, W_out, out, BB, NCC, EE, b_out);
    }
}